// round 14
// baseline (speedup 1.0000x reference)
#include <cuda_runtime.h>

#define BATCH 2
#define NPTS  4096
#define NTOT  (BATCH*NPTS)

#define LOG2E_F 1.4426950408889634f
#define LN2_F   0.6931471805599453f
#define LOGW_F  (-8.317766166719343f)   /* -ln(4096), uniform weights both sides */

typedef unsigned long long u64;

// Packed point data: (x, y, z, 0.5*|p|^2). side 0 = true_data (x), side 1 = particles (y)
__device__ float4 g_PX[NTOT];
__device__ float4 g_PY[NTOT];
// Interleaved column geometry: per pair p (cols 2p,2p+1): [qx_2p, qx_2p+1, qy_2p, qy_2p+1]
__device__ __align__(16) float g_qxy[2][2*NTOT];
// qz per side (u64 pair loads)
__device__ __align__(16) float g_qz[2][NTOT];
// Per-task precomputed column term tj = (dual_j - 0.5|q_j|^2) * log2e/eps, double-buffered
__device__ __align__(16) float g_tj[2][4][NTOT];
// Dual potentials, double-buffered: which: 0=a_y, 1=b_x, 2=a_x, 3=b_y
__device__ float g_dual[2][4][NTOT];
// finalize partials
__device__ double g_part[16];

// ---- f32x2 packed helpers (sm_103a) ----
__device__ __forceinline__ u64 pack2(float lo, float hi){
    u64 r;
    asm("mov.b64 %0, {%1, %2};" : "=l"(r)
        : "r"(__float_as_uint(lo)), "r"(__float_as_uint(hi)));
    return r;
}
__device__ __forceinline__ void unpack2(u64 v, float &lo, float &hi){
    unsigned int a, b;
    asm("mov.b64 {%0, %1}, %2;" : "=r"(a), "=r"(b) : "l"(v));
    lo = __uint_as_float(a); hi = __uint_as_float(b);
}
__device__ __forceinline__ u64 ffma2(u64 a, u64 b, u64 c){
    u64 d;
    asm("fma.rn.f32x2 %0, %1, %2, %3;" : "=l"(d) : "l"(a), "l"(b), "l"(c));
    return d;
}
__device__ __forceinline__ u64 fadd2(u64 a, u64 b){
    u64 d;
    asm("add.rn.f32x2 %0, %1, %2;" : "=l"(d) : "l"(a), "l"(b));
    return d;
}
__device__ __forceinline__ float ex2f(float x){ float r; asm("ex2.approx.ftz.f32 %0, %1;" : "=f"(r) : "f"(x)); return r; }
__device__ __forceinline__ float lg2f(float x){ float r; asm("lg2.approx.f32 %0, %1;"     : "=f"(r) : "f"(x)); return r; }

// Build packed points, interleaved columns, and the tj arrays for the FIRST launch
__global__ void pack_kernel(const float* __restrict__ x, const float* __restrict__ y,
                            float s2_0){
    int i = blockIdx.x*blockDim.x + threadIdx.x;
    if (i < NTOT){
        int p = i >> 1, lane = i & 1;
        float a = x[3*i+0], b = x[3*i+1], c = x[3*i+2];
        float w = 0.5f*(a*a + b*b + c*c);
        g_PX[i] = make_float4(a, b, c, w);
        g_qxy[0][4*p + lane]     = a;
        g_qxy[0][4*p + 2 + lane] = b;
        g_qz[0][i] = c;
        g_tj[0][0][i] = -w * s2_0;           // task0 columns = X side
        g_tj[0][2][i] = -w * s2_0;           // task2 columns = X side
        a = y[3*i+0]; b = y[3*i+1]; c = y[3*i+2];
        w = 0.5f*(a*a + b*b + c*c);
        g_PY[i] = make_float4(a, b, c, w);
        g_qxy[1][4*p + lane]     = a;
        g_qxy[1][4*p + 2 + lane] = b;
        g_qz[1][i] = c;
        g_tj[0][1][i] = -w * s2_0;           // task1 columns = Y side
        g_tj[0][3][i] = -w * s2_0;           // task3 columns = Y side
    }
}

// One launch = one stage: 4 softmin tasks x 2 batches x 1024 row-blocks of 4 rows.
// task 0: a_y' (P=Y, cols=X)  task 1: b_x' (P=X, cols=Y)
// task 2: a_x' (P=X, cols=X)  task 3: b_y' (P=Y, cols=Y)
// mode 0: plain store (init); mode 1: 0.5*(old+new); mode 2: plain store (final).
// Epilogue writes NEXT launch's tj (scaled by s2n) into g_tj[rdbuf^1].
__global__ __launch_bounds__(256, 3)
void softmin_kernel(float eps, float s2n, int src, int dst, int rdbuf, int mode)
{
    __shared__ float sred[8][4];
    __shared__ float sbro[4];

    const int tid    = threadIdx.x;
    const int rowblk = blockIdx.x & 1023;    // 1024 row-blocks of 4 rows
    const int combo  = blockIdx.x >> 10;     // 0..7
    const int task   = combo >> 1;
    const int batch  = combo & 1;
    const int base   = batch * NPTS;

    const float s2 = (1.0f / eps) * LOG2E_F;

    const int side = (task == 0 || task == 2) ? 0 : 1;   // column side
    const float4* P = (task == 0 || task == 3) ? (g_PY + base) : (g_PX + base);
    const int which = task;                               // dual slot this task writes
    float* outp = g_dual[dst][which] + base;
    const float* oldp = g_dual[src][which] + base;

    const ulonglong2* __restrict__ qxy2 = (const ulonglong2*)(g_qxy[side] + 2*base) + tid;
    const u64* __restrict__ qz2 = (const u64*)(g_qz[side] + base) + tid;
    const u64* __restrict__ tj2 = (const u64*)(g_tj[rdbuf][task] + base) + tid;

    const int row0 = rowblk * 4;

    // Loop-invariant packed row constants (p scaled into log2 domain).
    u64 pxx[4], pyy[4], pzz[4];
#pragma unroll
    for (int r = 0; r < 4; r++){
        float4 p = P[row0 + r];
        float a = p.x * s2, b = p.y * s2, c = p.z * s2;
        pxx[r] = pack2(a, a);
        pyy[r] = pack2(b, b);
        pzz[r] = pack2(c, c);
    }

    // ---------------- pass 1: row maxima ----------------
    float m_lo[4], m_hi[4];
#pragma unroll
    for (int r = 0; r < 4; r++){ m_lo[r] = -3.0e38f; m_hi[r] = -3.0e38f; }

#pragma unroll 4
    for (int k = 0; k < 8; k++){
        ulonglong2 xy = qxy2[k << 8];
        u64 qzv = qz2[k << 8], tjv = tj2[k << 8];
#pragma unroll
        for (int r = 0; r < 4; r++){
            u64 v2 = ffma2(pxx[r], xy.x, ffma2(pyy[r], xy.y, ffma2(pzz[r], qzv, tjv)));
            float lo, hi; unpack2(v2, lo, hi);
            m_lo[r] = fmaxf(m_lo[r], lo);
            m_hi[r] = fmaxf(m_hi[r], hi);
        }
    }

#pragma unroll
    for (int r = 0; r < 4; r++){
        float v = fmaxf(m_lo[r], m_hi[r]);
#pragma unroll
        for (int o = 16; o; o >>= 1) v = fmaxf(v, __shfl_xor_sync(0xffffffffu, v, o));
        if ((tid & 31) == 0) sred[tid >> 5][r] = v;
    }
    __syncthreads();
    if (tid < 4){
        float v = sred[0][tid];
#pragma unroll
        for (int w = 1; w < 8; w++) v = fmaxf(v, sred[w][tid]);
        sbro[tid] = v;
    }
    __syncthreads();

    u64 nM2[4];
#pragma unroll
    for (int r = 0; r < 4; r++){
        float nm = -sbro[r];
        nM2[r] = pack2(nm, nm);
    }

    // ---------------- pass 2: sum of exp2(v - M), packed accumulation ----------------
    u64 sacc[4];
#pragma unroll
    for (int r = 0; r < 4; r++) sacc[r] = 0ull;

#pragma unroll 4
    for (int k = 0; k < 8; k++){
        ulonglong2 xy = qxy2[k << 8];
        u64 qzv = qz2[k << 8], tjv = tj2[k << 8];
#pragma unroll
        for (int r = 0; r < 4; r++){
            u64 v2 = ffma2(pxx[r], xy.x, ffma2(pyy[r], xy.y, ffma2(pzz[r], qzv, tjv)));
            u64 w2 = fadd2(v2, nM2[r]);
            float lo, hi; unpack2(w2, lo, hi);
            float elo = ex2f(lo);
            float ehi = ex2f(hi);
            sacc[r] = fadd2(sacc[r], pack2(elo, ehi));   // pack2 = register pairing
        }
    }

#pragma unroll
    for (int r = 0; r < 4; r++){
        float lo, hi; unpack2(sacc[r], lo, hi);
        float v = lo + hi;
#pragma unroll
        for (int o = 16; o; o >>= 1) v += __shfl_xor_sync(0xffffffffu, v, o);
        if ((tid & 31) == 0) sred[tid >> 5][r] = v;
    }
    __syncthreads();
    if (tid < 4){
        float v = 0.0f;
#pragma unroll
        for (int w = 0; w < 8; w++) v += sred[w][tid];
        float4 p  = P[row0 + tid];
        float rbv = LOGW_F * LOG2E_F - p.w * s2;   // (logw - 0.5|p|^2/eps)*log2e
        float res = -(eps * LN2_F) * (rbv + sbro[tid] + lg2f(v));
        int row = row0 + tid;
        if (mode == 1) res = 0.5f * (oldp[row] + res);
        outp[row] = res;
        // Next launch's tj for the tj-array this task's dual feeds:
        // T[0] <- b_x (task1), T[1] <- a_y (task0), T[2] <- a_x (task2), T[3] <- b_y (task3)
        int tjt = (task == 0) ? 1 : (task == 1) ? 0 : task;
        g_tj[rdbuf ^ 1][tjt][base + row] = (res - p.w) * s2n;
    }
}

// F = sum_b [ mean_i(b_x - a_x) + mean_j(a_y - b_y) ] — 16-block partials
__global__ void finalize_part(int buf)
{
    const int tid = threadIdx.x;
    const int blk = blockIdx.x;                 // 0..15
    const float* ay = g_dual[buf][0];
    const float* bx = g_dual[buf][1];
    const float* ax = g_dual[buf][2];
    const float* by = g_dual[buf][3];
    double acc = 0.0;
    const int i0 = blk * (NTOT / 16);
#pragma unroll 2
    for (int t = tid; t < NTOT / 16; t += 256){
        int i = i0 + t;
        acc += (double)bx[i] - (double)ax[i];
        acc += (double)ay[i] - (double)by[i];
    }
    __shared__ double sd[8];
#pragma unroll
    for (int o = 16; o; o >>= 1) acc += __shfl_xor_sync(0xffffffffu, acc, o);
    if ((tid & 31) == 0) sd[tid >> 5] = acc;
    __syncthreads();
    if (tid == 0){
        double t = 0.0;
        for (int w = 0; w < 8; w++) t += sd[w];
        g_part[blk] = t;
    }
}

__global__ void finalize_sum(float* __restrict__ out)
{
    if (threadIdx.x == 0){
        double t = 0.0;
        for (int b = 0; b < 16; b++) t += g_part[b];
        out[0] = (float)(t / 4096.0);
    }
}

extern "C" void kernel_launch(void* const* d_in, const int* in_sizes, int n_in,
                              void* d_out, int out_size)
{
    const float* x = (const float*)d_in[0];   // true_data
    const float* y = (const float*)d_in[1];   // particles
    float* out = (float*)d_out;

    // Launch eps sequence: init(16), 9 annealing steps, final extrapolation(0.0025)
    const float E[11] = {16.0f,
                         16.0f, 16.0f, 4.0f, 1.0f, 0.25f,
                         0.0625f, 0.015625f, 0.00390625f, 0.0025f,
                         0.0025f};

    pack_kernel<<<(NTOT + 255)/256, 256>>>(x, y, LOG2E_F / E[0]);

    int cur = 0, rb = 0;
    // L0: init (mode 0) -> dual buffer 0; writes tj for L1 (eps E[1])
    softmin_kernel<<<8192, 256>>>(E[0], LOG2E_F / E[1], 0, 0, rb, 0);
    rb ^= 1;
    // L1..L9: annealing (mode 1, averaged, double-buffered duals)
    for (int i = 1; i <= 9; i++){
        softmin_kernel<<<8192, 256>>>(E[i], LOG2E_F / E[i + 1], cur, cur ^ 1, rb, 1);
        cur ^= 1; rb ^= 1;
    }
    // L10: final extrapolation (mode 2)
    softmin_kernel<<<8192, 256>>>(E[10], LOG2E_F / E[10], cur, cur ^ 1, rb, 2);
    cur ^= 1;

    finalize_part<<<16, 256>>>(cur);
    finalize_sum<<<1, 32>>>(out);
}

// round 16
// speedup vs baseline: 1.0038x; 1.0038x over previous
#include <cuda_runtime.h>

#define BATCH 2
#define NPTS  4096
#define NTOT  (BATCH*NPTS)

#define LOG2E_F 1.4426950408889634f
#define LN2_F   0.6931471805599453f
#define LOGW_F  (-8.317766166719343f)   /* -ln(4096), uniform weights both sides */

typedef unsigned long long u64;

// Packed point data: (x, y, z, 0.5*|p|^2). side 0 = true_data (x), side 1 = particles (y)
__device__ float4 g_PX[NTOT];
__device__ float4 g_PY[NTOT];
// DUPLICATED column geometry: qxd[2j] = qxd[2j+1] = qx_j  -> one LDG.64 = broadcast pair
__device__ __align__(16) float g_qxd[2][2*NTOT];
__device__ __align__(16) float g_qyd[2][2*NTOT];
__device__ __align__(16) float g_qzd[2][2*NTOT];
// Per-task duplicated column term tj = (dual_j - 0.5|q_j|^2)*log2e/eps, double-buffered
__device__ __align__(16) float g_tjd[2][4][2*NTOT];
// Dual potentials, double-buffered: which: 0=a_y, 1=b_x, 2=a_x, 3=b_y
__device__ float g_dual[2][4][NTOT];
// finalize partials
__device__ double g_part[16];

// ---- f32x2 packed helpers (sm_103a) ----
__device__ __forceinline__ u64 pack2(float lo, float hi){
    u64 r;
    asm("mov.b64 %0, {%1, %2};" : "=l"(r)
        : "r"(__float_as_uint(lo)), "r"(__float_as_uint(hi)));
    return r;
}
__device__ __forceinline__ void unpack2(u64 v, float &lo, float &hi){
    unsigned int a, b;
    asm("mov.b64 {%0, %1}, %2;" : "=r"(a), "=r"(b) : "l"(v));
    lo = __uint_as_float(a); hi = __uint_as_float(b);
}
__device__ __forceinline__ u64 ffma2(u64 a, u64 b, u64 c){
    u64 d;
    asm("fma.rn.f32x2 %0, %1, %2, %3;" : "=l"(d) : "l"(a), "l"(b), "l"(c));
    return d;
}
__device__ __forceinline__ u64 fadd2(u64 a, u64 b){
    u64 d;
    asm("add.rn.f32x2 %0, %1, %2;" : "=l"(d) : "l"(a), "l"(b));
    return d;
}
__device__ __forceinline__ float ex2f(float x){ float r; asm("ex2.approx.ftz.f32 %0, %1;" : "=f"(r) : "f"(x)); return r; }
__device__ __forceinline__ float lg2f(float x){ float r; asm("lg2.approx.f32 %0, %1;"     : "=f"(r) : "f"(x)); return r; }

// Build packed points, duplicated columns, and tj arrays for the FIRST launch
__global__ void pack_kernel(const float* __restrict__ x, const float* __restrict__ y,
                            float s2_0){
    int i = blockIdx.x*blockDim.x + threadIdx.x;
    if (i < NTOT){
        float a = x[3*i+0], b = x[3*i+1], c = x[3*i+2];
        float w = 0.5f*(a*a + b*b + c*c);
        g_PX[i] = make_float4(a, b, c, w);
        g_qxd[0][2*i] = a; g_qxd[0][2*i+1] = a;
        g_qyd[0][2*i] = b; g_qyd[0][2*i+1] = b;
        g_qzd[0][2*i] = c; g_qzd[0][2*i+1] = c;
        float t0 = -w * s2_0;
        g_tjd[0][0][2*i] = t0; g_tjd[0][0][2*i+1] = t0;  // task0 cols = X side
        g_tjd[0][2][2*i] = t0; g_tjd[0][2][2*i+1] = t0;  // task2 cols = X side
        a = y[3*i+0]; b = y[3*i+1]; c = y[3*i+2];
        w = 0.5f*(a*a + b*b + c*c);
        g_PY[i] = make_float4(a, b, c, w);
        g_qxd[1][2*i] = a; g_qxd[1][2*i+1] = a;
        g_qyd[1][2*i] = b; g_qyd[1][2*i+1] = b;
        g_qzd[1][2*i] = c; g_qzd[1][2*i+1] = c;
        t0 = -w * s2_0;
        g_tjd[0][1][2*i] = t0; g_tjd[0][1][2*i+1] = t0;  // task1 cols = Y side
        g_tjd[0][3][2*i] = t0; g_tjd[0][3][2*i+1] = t0;  // task3 cols = Y side
    }
}

// One launch = one stage: 4 softmin tasks x 2 batches x 512 row-blocks of 8 rows.
// Rows are packed in PAIRS per f32x2 lane: pr = 0..3 covers rows (2pr, 2pr+1).
// task 0: a_y' (P=Y, cols=X)  task 1: b_x' (P=X, cols=Y)
// task 2: a_x' (P=X, cols=X)  task 3: b_y' (P=Y, cols=Y)
// mode 0: plain store (init); mode 1: 0.5*(old+new); mode 2: plain store (final).
// Epilogue writes NEXT launch's duplicated tj (scaled by s2n) into g_tjd[rdbuf^1].
__global__ __launch_bounds__(256, 3)
void softmin_kernel(float eps, float s2n, int src, int dst, int rdbuf, int mode)
{
    __shared__ float sred[8][8];
    __shared__ float sbro[8];

    const int tid    = threadIdx.x;
    const int rowblk = blockIdx.x & 511;     // 512 row-blocks of 8 rows
    const int combo  = blockIdx.x >> 9;      // 0..7
    const int task   = combo >> 1;
    const int batch  = combo & 1;
    const int base   = batch * NPTS;

    const float s2 = (1.0f / eps) * LOG2E_F;

    const int side = (task == 0 || task == 2) ? 0 : 1;   // column side
    const float4* P = (task == 0 || task == 3) ? (g_PY + base) : (g_PX + base);
    const int which = task;                               // dual slot this task writes
    float* outp = g_dual[dst][which] + base;
    const float* oldp = g_dual[src][which] + base;

    // duplicated arrays: u64 index j -> (val_j, val_j)
    const u64* __restrict__ qx2 = (const u64*)(g_qxd[side] + 2*base) + tid;
    const u64* __restrict__ qy2 = (const u64*)(g_qyd[side] + 2*base) + tid;
    const u64* __restrict__ qz2 = (const u64*)(g_qzd[side] + 2*base) + tid;
    const u64* __restrict__ tj2 = (const u64*)(g_tjd[rdbuf][task] + 2*base) + tid;

    const int row0 = rowblk * 8;

    // Loop-invariant packed ROW-PAIR constants (scaled into log2 domain).
    u64 pxx[4], pyy[4], pzz[4];
#pragma unroll
    for (int pr = 0; pr < 4; pr++){
        float4 p0 = P[row0 + 2*pr];
        float4 p1 = P[row0 + 2*pr + 1];
        pxx[pr] = pack2(p0.x * s2, p1.x * s2);
        pyy[pr] = pack2(p0.y * s2, p1.y * s2);
        pzz[pr] = pack2(p0.z * s2, p1.z * s2);
    }

    // ---------------- pass 1: row maxima ----------------
    float m_lo[4], m_hi[4];
#pragma unroll
    for (int pr = 0; pr < 4; pr++){ m_lo[pr] = -3.0e38f; m_hi[pr] = -3.0e38f; }

#pragma unroll 2
    for (int k = 0; k < 16; k++){
        u64 qxv = qx2[k << 8], qyv = qy2[k << 8], qzv = qz2[k << 8], tjv = tj2[k << 8];
#pragma unroll
        for (int pr = 0; pr < 4; pr++){
            u64 v2 = ffma2(pxx[pr], qxv, ffma2(pyy[pr], qyv, ffma2(pzz[pr], qzv, tjv)));
            float lo, hi; unpack2(v2, lo, hi);
            m_lo[pr] = fmaxf(m_lo[pr], lo);   // row 2pr
            m_hi[pr] = fmaxf(m_hi[pr], hi);   // row 2pr+1
        }
    }

#pragma unroll
    for (int r = 0; r < 8; r++){
        float v = (r & 1) ? m_hi[r >> 1] : m_lo[r >> 1];
#pragma unroll
        for (int o = 16; o; o >>= 1) v = fmaxf(v, __shfl_xor_sync(0xffffffffu, v, o));
        if ((tid & 31) == 0) sred[tid >> 5][r] = v;
    }
    __syncthreads();
    if (tid < 8){
        float v = sred[0][tid];
#pragma unroll
        for (int w = 1; w < 8; w++) v = fmaxf(v, sred[w][tid]);
        sbro[tid] = v;
    }
    __syncthreads();

    u64 nM2[4];
#pragma unroll
    for (int pr = 0; pr < 4; pr++)
        nM2[pr] = pack2(-sbro[2*pr], -sbro[2*pr + 1]);

    // ---------------- pass 2: sum of exp2(v - M), packed accumulation ----------------
    u64 sacc[4];
#pragma unroll
    for (int pr = 0; pr < 4; pr++) sacc[pr] = 0ull;

#pragma unroll 2
    for (int k = 0; k < 16; k++){
        u64 qxv = qx2[k << 8], qyv = qy2[k << 8], qzv = qz2[k << 8], tjv = tj2[k << 8];
#pragma unroll
        for (int pr = 0; pr < 4; pr++){
            u64 v2 = ffma2(pxx[pr], qxv, ffma2(pyy[pr], qyv, ffma2(pzz[pr], qzv, tjv)));
            u64 w2 = fadd2(v2, nM2[pr]);
            float lo, hi; unpack2(w2, lo, hi);
            float elo = ex2f(lo);
            float ehi = ex2f(hi);
            sacc[pr] = fadd2(sacc[pr], pack2(elo, ehi));
        }
    }

#pragma unroll
    for (int r = 0; r < 8; r++){
        float lo, hi; unpack2(sacc[r >> 1], lo, hi);
        float v = (r & 1) ? hi : lo;
#pragma unroll
        for (int o = 16; o; o >>= 1) v += __shfl_xor_sync(0xffffffffu, v, o);
        if ((tid & 31) == 0) sred[tid >> 5][r] = v;
    }
    __syncthreads();
    if (tid < 8){
        float v = 0.0f;
#pragma unroll
        for (int w = 0; w < 8; w++) v += sred[w][tid];
        float4 p  = P[row0 + tid];
        float rbv = LOGW_F * LOG2E_F - p.w * s2;   // (logw - 0.5|p|^2/eps)*log2e
        float res = -(eps * LN2_F) * (rbv + sbro[tid] + lg2f(v));
        int row = row0 + tid;
        if (mode == 1) res = 0.5f * (oldp[row] + res);
        outp[row] = res;
        // Next launch's duplicated tj for the array this task's dual feeds:
        // T[0] <- b_x (task1), T[1] <- a_y (task0), T[2] <- a_x (task2), T[3] <- b_y (task3)
        int tjt = (task == 0) ? 1 : (task == 1) ? 0 : task;
        float tv = (res - p.w) * s2n;
        g_tjd[rdbuf ^ 1][tjt][2*(base + row)]     = tv;
        g_tjd[rdbuf ^ 1][tjt][2*(base + row) + 1] = tv;
    }
}

// F = sum_b [ mean_i(b_x - a_x) + mean_j(a_y - b_y) ] — 16-block partials
__global__ void finalize_part(int buf)
{
    const int tid = threadIdx.x;
    const int blk = blockIdx.x;                 // 0..15
    const float* ay = g_dual[buf][0];
    const float* bx = g_dual[buf][1];
    const float* ax = g_dual[buf][2];
    const float* by = g_dual[buf][3];
    double acc = 0.0;
    const int i0 = blk * (NTOT / 16);
#pragma unroll 2
    for (int t = tid; t < NTOT / 16; t += 256){
        int i = i0 + t;
        acc += (double)bx[i] - (double)ax[i];
        acc += (double)ay[i] - (double)by[i];
    }
    __shared__ double sd[8];
#pragma unroll
    for (int o = 16; o; o >>= 1) acc += __shfl_xor_sync(0xffffffffu, acc, o);
    if ((tid & 31) == 0) sd[tid >> 5] = acc;
    __syncthreads();
    if (tid == 0){
        double t = 0.0;
        for (int w = 0; w < 8; w++) t += sd[w];
        g_part[blk] = t;
    }
}

__global__ void finalize_sum(float* __restrict__ out)
{
    if (threadIdx.x == 0){
        double t = 0.0;
        for (int b = 0; b < 16; b++) t += g_part[b];
        out[0] = (float)(t / 4096.0);
    }
}

extern "C" void kernel_launch(void* const* d_in, const int* in_sizes, int n_in,
                              void* d_out, int out_size)
{
    const float* x = (const float*)d_in[0];   // true_data
    const float* y = (const float*)d_in[1];   // particles
    float* out = (float*)d_out;

    // Launch eps sequence: init(16), 9 annealing steps, final extrapolation(0.0025)
    const float E[11] = {16.0f,
                         16.0f, 16.0f, 4.0f, 1.0f, 0.25f,
                         0.0625f, 0.015625f, 0.00390625f, 0.0025f,
                         0.0025f};

    pack_kernel<<<(NTOT + 255)/256, 256>>>(x, y, LOG2E_F / E[0]);

    int cur = 0, rb = 0;
    // L0: init (mode 0) -> dual buffer 0; writes tj for L1 (eps E[1])
    softmin_kernel<<<4096, 256>>>(E[0], LOG2E_F / E[1], 0, 0, rb, 0);
    rb ^= 1;
    // L1..L9: annealing (mode 1, averaged, double-buffered duals)
    for (int i = 1; i <= 9; i++){
        softmin_kernel<<<4096, 256>>>(E[i], LOG2E_F / E[i + 1], cur, cur ^ 1, rb, 1);
        cur ^= 1; rb ^= 1;
    }
    // L10: final extrapolation (mode 2)
    softmin_kernel<<<4096, 256>>>(E[10], LOG2E_F / E[10], cur, cur ^ 1, rb, 2);
    cur ^= 1;

    finalize_part<<<16, 256>>>(cur);
    finalize_sum<<<1, 32>>>(out);
}

// round 17
// speedup vs baseline: 1.1364x; 1.1321x over previous
#include <cuda_runtime.h>

#define BATCH 2
#define NPTS  4096
#define NTOT  (BATCH*NPTS)

#define LOG2E_F 1.4426950408889634f
#define LN2_F   0.6931471805599453f
#define LOGW_F  (-8.317766166719343f)   /* -ln(4096), uniform weights both sides */

typedef unsigned long long u64;

// Packed point data: (x, y, z, 0.5*|p|^2). side 0 = true_data (x), side 1 = particles (y)
__device__ float4 g_PX[NTOT];
__device__ float4 g_PY[NTOT];
// Interleaved column records, one 16B record per column PAIR p (cols 2p, 2p+1):
//   g_qxy[side][p] = { qx_2p, qx_2p+1, qy_2p, qy_2p+1 }
__device__ __align__(16) float g_qxy[2][2*NTOT];
// Per-task interleaved record: { qz_2p, qz_2p+1, tj_2p, tj_2p+1 }, double-buffered.
// qz halves are filled once by pack_kernel (both buffers); tj halves are rewritten
// each stage by the epilogue. tj = (dual_j - 0.5|q_j|^2) * log2e/eps.
__device__ __align__(16) float g_ztj[2][4][2*NTOT];
// Dual potentials, double-buffered: which: 0=a_y, 1=b_x, 2=a_x, 3=b_y
__device__ float g_dual[2][4][NTOT];
// finalize partials
__device__ double g_part[16];

// ---- f32x2 packed helpers (sm_103a) ----
__device__ __forceinline__ u64 pack2(float lo, float hi){
    u64 r;
    asm("mov.b64 %0, {%1, %2};" : "=l"(r)
        : "r"(__float_as_uint(lo)), "r"(__float_as_uint(hi)));
    return r;
}
__device__ __forceinline__ void unpack2(u64 v, float &lo, float &hi){
    unsigned int a, b;
    asm("mov.b64 {%0, %1}, %2;" : "=r"(a), "=r"(b) : "l"(v));
    lo = __uint_as_float(a); hi = __uint_as_float(b);
}
__device__ __forceinline__ u64 ffma2(u64 a, u64 b, u64 c){
    u64 d;
    asm("fma.rn.f32x2 %0, %1, %2, %3;" : "=l"(d) : "l"(a), "l"(b), "l"(c));
    return d;
}
__device__ __forceinline__ u64 fadd2(u64 a, u64 b){
    u64 d;
    asm("add.rn.f32x2 %0, %1, %2;" : "=l"(d) : "l"(a), "l"(b));
    return d;
}
__device__ __forceinline__ float ex2f(float x){ float r; asm("ex2.approx.ftz.f32 %0, %1;" : "=f"(r) : "f"(x)); return r; }
__device__ __forceinline__ float lg2f(float x){ float r; asm("lg2.approx.f32 %0, %1;"     : "=f"(r) : "f"(x)); return r; }

// Build packed points, interleaved column records, and tj for the FIRST launch
__global__ void pack_kernel(const float* __restrict__ x, const float* __restrict__ y,
                            float s2_0){
    int i = blockIdx.x*blockDim.x + threadIdx.x;
    if (i < NTOT){
        int p = i >> 1, lane = i & 1;
        float a = x[3*i+0], b = x[3*i+1], c = x[3*i+2];
        float w = 0.5f*(a*a + b*b + c*c);
        g_PX[i] = make_float4(a, b, c, w);
        g_qxy[0][4*p + lane]     = a;
        g_qxy[0][4*p + 2 + lane] = b;
        float t0 = -w * s2_0;
        // X side feeds tasks 0 and 2
        g_ztj[0][0][4*p + lane] = c;  g_ztj[1][0][4*p + lane] = c;
        g_ztj[0][2][4*p + lane] = c;  g_ztj[1][2][4*p + lane] = c;
        g_ztj[0][0][4*p + 2 + lane] = t0;
        g_ztj[0][2][4*p + 2 + lane] = t0;
        a = y[3*i+0]; b = y[3*i+1]; c = y[3*i+2];
        w = 0.5f*(a*a + b*b + c*c);
        g_PY[i] = make_float4(a, b, c, w);
        g_qxy[1][4*p + lane]     = a;
        g_qxy[1][4*p + 2 + lane] = b;
        t0 = -w * s2_0;
        // Y side feeds tasks 1 and 3
        g_ztj[0][1][4*p + lane] = c;  g_ztj[1][1][4*p + lane] = c;
        g_ztj[0][3][4*p + lane] = c;  g_ztj[1][3][4*p + lane] = c;
        g_ztj[0][1][4*p + 2 + lane] = t0;
        g_ztj[0][3][4*p + 2 + lane] = t0;
    }
}

// One launch = one stage: 4 softmin tasks x 2 batches x 512 row-blocks of 8 rows.
// Columns packed in PAIRS per f32x2 lane.
// task 0: a_y' (P=Y, cols=X)  task 1: b_x' (P=X, cols=Y)
// task 2: a_x' (P=X, cols=X)  task 3: b_y' (P=Y, cols=Y)
// mode 0: plain store (init); mode 1: 0.5*(old+new); mode 2: plain store (final).
// Epilogue writes NEXT launch's tj (scaled by s2n) into g_ztj[rdbuf^1].
__global__ __launch_bounds__(256, 2)
void softmin_kernel(float eps, float s2n, int src, int dst, int rdbuf, int mode)
{
    __shared__ float sred[8][8];
    __shared__ float sbro[8];

    const int tid    = threadIdx.x;
    const int rowblk = blockIdx.x & 511;     // 512 row-blocks of 8 rows
    const int combo  = blockIdx.x >> 9;      // 0..7
    const int task   = combo >> 1;
    const int batch  = combo & 1;
    const int base   = batch * NPTS;

    const float s2 = (1.0f / eps) * LOG2E_F;

    const int side = (task == 0 || task == 2) ? 0 : 1;   // column side
    const float4* P = (task == 0 || task == 3) ? (g_PY + base) : (g_PX + base);
    const int which = task;                               // dual slot this task writes
    float* outp = g_dual[dst][which] + base;
    const float* oldp = g_dual[src][which] + base;

    const ulonglong2* __restrict__ qxy2 = (const ulonglong2*)(g_qxy[side] + 2*base) + tid;
    const ulonglong2* __restrict__ ztj2 = (const ulonglong2*)(g_ztj[rdbuf][task] + 2*base) + tid;

    const int row0 = rowblk * 8;

    // Loop-invariant packed row constants (p scaled into log2 domain), duplicated
    // per lane because columns occupy the f32x2 lanes.
    u64 pxx[8], pyy[8], pzz[8];
#pragma unroll
    for (int r = 0; r < 8; r++){
        float4 p = P[row0 + r];
        float a = p.x * s2, b = p.y * s2, c = p.z * s2;
        pxx[r] = pack2(a, a);
        pyy[r] = pack2(b, b);
        pzz[r] = pack2(c, c);
    }

    // ---------------- pass 1: row maxima ----------------
    float m_lo[8], m_hi[8];
#pragma unroll
    for (int r = 0; r < 8; r++){ m_lo[r] = -3.0e38f; m_hi[r] = -3.0e38f; }

#pragma unroll
    for (int k = 0; k < 8; k++){
        ulonglong2 xy = qxy2[k << 8];        // .x = qx pair, .y = qy pair
        ulonglong2 zt = ztj2[k << 8];        // .x = qz pair, .y = tj pair
#pragma unroll
        for (int r = 0; r < 8; r++){
            u64 v2 = ffma2(pxx[r], xy.x, ffma2(pyy[r], xy.y, ffma2(pzz[r], zt.x, zt.y)));
            float lo, hi; unpack2(v2, lo, hi);
            m_lo[r] = fmaxf(m_lo[r], lo);
            m_hi[r] = fmaxf(m_hi[r], hi);
        }
    }

#pragma unroll
    for (int r = 0; r < 8; r++){
        float v = fmaxf(m_lo[r], m_hi[r]);
#pragma unroll
        for (int o = 16; o; o >>= 1) v = fmaxf(v, __shfl_xor_sync(0xffffffffu, v, o));
        if ((tid & 31) == 0) sred[tid >> 5][r] = v;
    }
    __syncthreads();
    if (tid < 8){
        float v = sred[0][tid];
#pragma unroll
        for (int w = 1; w < 8; w++) v = fmaxf(v, sred[w][tid]);
        sbro[tid] = v;
    }
    __syncthreads();

    u64 nM2[8];
#pragma unroll
    for (int r = 0; r < 8; r++){
        float nm = -sbro[r];
        nM2[r] = pack2(nm, nm);
    }

    // ---------------- pass 2: sum of exp2(v - M), packed accumulation ----------------
    u64 sacc[8];
#pragma unroll
    for (int r = 0; r < 8; r++) sacc[r] = 0ull;

#pragma unroll
    for (int k = 0; k < 8; k++){
        ulonglong2 xy = qxy2[k << 8];
        ulonglong2 zt = ztj2[k << 8];
#pragma unroll
        for (int r = 0; r < 8; r++){
            u64 v2 = ffma2(pxx[r], xy.x, ffma2(pyy[r], xy.y, ffma2(pzz[r], zt.x, zt.y)));
            u64 w2 = fadd2(v2, nM2[r]);
            float lo, hi; unpack2(w2, lo, hi);
            float elo = ex2f(lo);
            float ehi = ex2f(hi);
            sacc[r] = fadd2(sacc[r], pack2(elo, ehi));   // pack2 = register pairing
        }
    }

#pragma unroll
    for (int r = 0; r < 8; r++){
        float lo, hi; unpack2(sacc[r], lo, hi);
        float v = lo + hi;
#pragma unroll
        for (int o = 16; o; o >>= 1) v += __shfl_xor_sync(0xffffffffu, v, o);
        if ((tid & 31) == 0) sred[tid >> 5][r] = v;
    }
    __syncthreads();
    if (tid < 8){
        float v = 0.0f;
#pragma unroll
        for (int w = 0; w < 8; w++) v += sred[w][tid];
        float4 p  = P[row0 + tid];
        float rbv = LOGW_F * LOG2E_F - p.w * s2;   // (logw - 0.5|p|^2/eps)*log2e
        float res = -(eps * LN2_F) * (rbv + sbro[tid] + lg2f(v));
        int row = row0 + tid;
        if (mode == 1) res = 0.5f * (oldp[row] + res);
        outp[row] = res;
        // Next launch's tj for the record this task's dual feeds:
        // T[0] <- b_x (task1), T[1] <- a_y (task0), T[2] <- a_x (task2), T[3] <- b_y (task3)
        int tjt = (task == 0) ? 1 : (task == 1) ? 0 : task;
        int i   = base + row;
        g_ztj[rdbuf ^ 1][tjt][4*(i >> 1) + 2 + (i & 1)] = (res - p.w) * s2n;
    }
}

// F = sum_b [ mean_i(b_x - a_x) + mean_j(a_y - b_y) ] — 16-block partials
__global__ void finalize_part(int buf)
{
    const int tid = threadIdx.x;
    const int blk = blockIdx.x;                 // 0..15
    const float* ay = g_dual[buf][0];
    const float* bx = g_dual[buf][1];
    const float* ax = g_dual[buf][2];
    const float* by = g_dual[buf][3];
    double acc = 0.0;
    const int i0 = blk * (NTOT / 16);
#pragma unroll 2
    for (int t = tid; t < NTOT / 16; t += 256){
        int i = i0 + t;
        acc += (double)bx[i] - (double)ax[i];
        acc += (double)ay[i] - (double)by[i];
    }
    __shared__ double sd[8];
#pragma unroll
    for (int o = 16; o; o >>= 1) acc += __shfl_xor_sync(0xffffffffu, acc, o);
    if ((tid & 31) == 0) sd[tid >> 5] = acc;
    __syncthreads();
    if (tid == 0){
        double t = 0.0;
        for (int w = 0; w < 8; w++) t += sd[w];
        g_part[blk] = t;
    }
}

__global__ void finalize_sum(float* __restrict__ out)
{
    if (threadIdx.x == 0){
        double t = 0.0;
        for (int b = 0; b < 16; b++) t += g_part[b];
        out[0] = (float)(t / 4096.0);
    }
}

extern "C" void kernel_launch(void* const* d_in, const int* in_sizes, int n_in,
                              void* d_out, int out_size)
{
    const float* x = (const float*)d_in[0];   // true_data
    const float* y = (const float*)d_in[1];   // particles
    float* out = (float*)d_out;

    // Launch eps sequence: init(16), 9 annealing steps, final extrapolation(0.0025)
    const float E[11] = {16.0f,
                         16.0f, 16.0f, 4.0f, 1.0f, 0.25f,
                         0.0625f, 0.015625f, 0.00390625f, 0.0025f,
                         0.0025f};

    pack_kernel<<<(NTOT + 255)/256, 256>>>(x, y, LOG2E_F / E[0]);

    int cur = 0, rb = 0;
    // L0: init (mode 0) -> dual buffer 0; writes tj for L1 (eps E[1])
    softmin_kernel<<<4096, 256>>>(E[0], LOG2E_F / E[1], 0, 0, rb, 0);
    rb ^= 1;
    // L1..L9: annealing (mode 1, averaged, double-buffered duals)
    for (int i = 1; i <= 9; i++){
        softmin_kernel<<<4096, 256>>>(E[i], LOG2E_F / E[i + 1], cur, cur ^ 1, rb, 1);
        cur ^= 1; rb ^= 1;
    }
    // L10: final extrapolation (mode 2)
    softmin_kernel<<<4096, 256>>>(E[10], LOG2E_F / E[10], cur, cur ^ 1, rb, 2);
    cur ^= 1;

    finalize_part<<<16, 256>>>(cur);
    finalize_sum<<<1, 32>>>(out);
}